// round 10
// baseline (speedup 1.0000x reference)
#include <cuda_runtime.h>
#include <cstdint>

#define N_NODES 50000
#define N_EDGES 600000
#define D 128
#define EPS 1e-5f

// ---------------- scratch (static device globals; no allocation) -------------
// NEVER passed as kernel arguments from host (host sees only the shadow
// variable; on GB300 ATS that silently writes host memory). All kernels
// reference these symbols directly in device code.
__device__ __align__(16) float g_xw[(size_t)N_NODES * D];   // x @ W^T
__device__ __align__(16) float g_agg[(size_t)N_NODES * D];  // scatter accumulator
__device__ float g_deg[N_NODES];
__device__ float g_dinv[N_NODES];
__device__ float g_colsum[D];
__device__ float g_colss[D];
__device__ float g_mean[D];
__device__ float g_scale;
__device__ int   g_is64;

// ---------------- edge dtype helper (int64 vs int32 storage) -----------------
// Detection (k_zero, thread 0): int64 little-endian node ids < 50000 have every
// odd 32-bit word zero; genuine int32 ids are random nonzero. 256 samples.
__device__ __forceinline__ int edge_at(const void* ei, int idx) {
    int v;
    if (g_is64) v = (int)__ldg(&((const long long*)ei)[idx]);
    else        v = __ldg(&((const int*)ei)[idx]);
    // clamp: any decode surprise degrades to wrong-answer, not a fault
    return (v < 0) ? 0 : (v >= N_NODES ? N_NODES - 1 : v);
}

// ---------------- zero scratch + dtype sniff (graph-replay safe) -------------
__global__ void k_zero(const int* __restrict__ ei32) {
    int idx = blockIdx.x * blockDim.x + threadIdx.x;
    int stride = gridDim.x * blockDim.x;
    if (idx == 0) {
        int all_zero = 1;
        for (int i = 0; i < 256; i++)
            if (__ldg(&ei32[2 * i + 1]) != 0) { all_zero = 0; break; }
        g_is64 = all_zero;
    }
    float4 z = make_float4(0.f, 0.f, 0.f, 0.f);
    float4* agg4 = reinterpret_cast<float4*>(g_agg);
    const int n4 = N_NODES * D / 4;
    for (int i = idx; i < n4; i += stride) agg4[i] = z;
    for (int i = idx; i < N_NODES; i += stride) g_deg[i] = 0.f;
    if (idx < D) { g_colsum[idx] = 0.f; g_colss[idx] = 0.f; }
}

// ---------------- degree count ----------------------------------------------
__global__ void k_degree(const void* __restrict__ ei) {
    int e = blockIdx.x * blockDim.x + threadIdx.x;
    if (e < N_EDGES) {
        int c = edge_at(ei, N_EDGES + e);  // col = target
        atomicAdd(&g_deg[c], 1.0f);
    }
}

__global__ void k_dinv() {
    int i = blockIdx.x * blockDim.x + threadIdx.x;
    if (i < N_NODES) g_dinv[i] = rsqrtf(g_deg[i] + 1.0f);  // +1 self loop
}

// ---------------- GEMM: g_xw = x @ W^T (fp32, 128x64x32 tile, 8x4/thread) ----
#define GM 128
#define GN 64
#define GK 32
__global__ __launch_bounds__(256) void k_gemm(const float* __restrict__ A,
                                              const float* __restrict__ Wm) {
    __shared__ float sA[GK][GM + 1];  // +1 pad: conflict-free transposed stores
    __shared__ float sB[GK][GN + 1];
    const int tid = threadIdx.x;
    const int brow = blockIdx.x * GM;
    const int bcol = blockIdx.y * GN;
    const int tx = tid & 15;   // col group: cols tx*4 .. tx*4+3
    const int ty = tid >> 4;   // row group: rows ty*8 .. ty*8+7

    float acc[8][4] = {};

    for (int k0 = 0; k0 < D; k0 += GK) {
#pragma unroll
        for (int p = 0; p < 4; p++) {            // A tile: 128 x 32
            int r  = (tid >> 3) + p * 32;
            int kk = (tid & 7) * 4;
            int gr = brow + r;
            float4 v = make_float4(0.f, 0.f, 0.f, 0.f);
            if (gr < N_NODES)
                v = *reinterpret_cast<const float4*>(A + (size_t)gr * D + k0 + kk);
            sA[kk + 0][r] = v.x; sA[kk + 1][r] = v.y;
            sA[kk + 2][r] = v.z; sA[kk + 3][r] = v.w;
        }
#pragma unroll
        for (int p = 0; p < 2; p++) {            // B tile: 64 x 32
            int r  = (tid >> 3) + p * 32;
            int kk = (tid & 7) * 4;
            float4 v = *reinterpret_cast<const float4*>(Wm + (size_t)(bcol + r) * D + k0 + kk);
            sB[kk + 0][r] = v.x; sB[kk + 1][r] = v.y;
            sB[kk + 2][r] = v.z; sB[kk + 3][r] = v.w;
        }
        __syncthreads();

#pragma unroll
        for (int kk = 0; kk < GK; kk++) {
            float a[8], b[4];
#pragma unroll
            for (int i = 0; i < 8; i++) a[i] = sA[kk][ty * 8 + i];
#pragma unroll
            for (int j = 0; j < 4; j++) b[j] = sB[kk][tx * 4 + j];
#pragma unroll
            for (int i = 0; i < 8; i++)
#pragma unroll
                for (int j = 0; j < 4; j++)
                    acc[i][j] = fmaf(a[i], b[j], acc[i][j]);
        }
        __syncthreads();
    }

#pragma unroll
    for (int i = 0; i < 8; i++) {
        int gr = brow + ty * 8 + i;
        if (gr < N_NODES) {
            float4 v = make_float4(acc[i][0], acc[i][1], acc[i][2], acc[i][3]);
            *reinterpret_cast<float4*>(g_xw + (size_t)gr * D + bcol + tx * 4) = v;
        }
    }
}

// ---------------- gather + scale + scatter-add (warp per edge) ---------------
__global__ __launch_bounds__(256) void k_scatter(const void* __restrict__ ei) {
    const int warp = (blockIdx.x * blockDim.x + threadIdx.x) >> 5;
    const int lane = threadIdx.x & 31;
    if (warp >= N_EDGES + N_NODES) return;

    int r, c;
    float norm;
    if (warp < N_EDGES) {
        r = edge_at(ei, warp);             // row = source
        c = edge_at(ei, N_EDGES + warp);   // col = target
        norm = g_dinv[r] * g_dinv[c];
    } else {
        r = c = warp - N_EDGES;            // self loop
        float d = g_dinv[r];
        norm = d * d;
    }

    const float4* src = reinterpret_cast<const float4*>(g_xw + (size_t)r * D);
    float4 v = src[lane];
    float4 m = make_float4(v.x * norm, v.y * norm, v.z * norm, v.w * norm);
    float4* dst = reinterpret_cast<float4*>(g_agg + (size_t)c * D) + lane;
#if __CUDA_ARCH__ >= 900
    atomicAdd(dst, m);                     // vector RED
#else
    float* d4 = reinterpret_cast<float*>(dst);
    atomicAdd(d4 + 0, m.x); atomicAdd(d4 + 1, m.y);
    atomicAdd(d4 + 2, m.z); atomicAdd(d4 + 3, m.w);
#endif
}

// ---------------- column stats: sum and sumsq per feature --------------------
__global__ __launch_bounds__(D) void k_stats() {
    const int c = threadIdx.x;  // 128 threads = one per column
    float s = 0.f, ss = 0.f;
    for (int r = blockIdx.x; r < N_NODES; r += gridDim.x) {
        float v = g_agg[(size_t)r * D + c];
        s += v;
        ss += v * v;
    }
    atomicAdd(&g_colsum[c], s);
    atomicAdd(&g_colss[c], ss);
}

__global__ __launch_bounds__(D) void k_finalize_stats() {
    const int c = threadIdx.x;
    float m = g_colsum[c] * (1.0f / N_NODES);
    g_mean[c] = m;
    // sum_i (v - m)^2 = sum v^2 - N m^2
    float ssc = g_colss[c] - (float)N_NODES * m * m;
    __shared__ float red[D];
    red[c] = ssc;
    __syncthreads();
    for (int off = D / 2; off > 0; off >>= 1) {
        if (c < off) red[c] += red[c + off];
        __syncthreads();
    }
    if (c == 0) g_scale = rsqrtf(EPS + red[0] * (1.0f / N_NODES));
}

// ---------------- normalize + relu + residual --------------------------------
__global__ void k_output(float* __restrict__ out) {
    const int idx = blockIdx.x * blockDim.x + threadIdx.x;  // float4 index
    const int n4 = N_NODES * D / 4;
    if (idx >= n4) return;
    const int c = (idx & (D / 4 - 1)) * 4;
    const float scale = g_scale;
    float4 v = reinterpret_cast<const float4*>(g_agg)[idx];
    float o0 = (v.x - g_mean[c + 0]) * scale;
    float o1 = (v.y - g_mean[c + 1]) * scale;
    float o2 = (v.z - g_mean[c + 2]) * scale;
    float o3 = (v.w - g_mean[c + 3]) * scale;
    float4 y;
    y.x = fmaxf(o0, 0.f) + o0;
    y.y = fmaxf(o1, 0.f) + o1;
    y.z = fmaxf(o2, 0.f) + o2;
    y.w = fmaxf(o3, 0.f) + o3;
    reinterpret_cast<float4*>(out)[idx] = y;
}

// ---------------- launch ------------------------------------------------------
extern "C" void kernel_launch(void* const* d_in, const int* in_sizes, int n_in,
                              void* d_out, int out_size) {
    // Identify inputs by element count, NOT by position:
    //   x: 50000*128 = 6,400,000   W: 128*128 = 16,384
    //   edge_index: 2*600000 = 1,200,000 (int64 or int32; dtype sniffed on device)
    const float* x  = nullptr;
    const float* Wm = nullptr;
    const void*  ei = nullptr;
    for (int i = 0; i < n_in; i++) {
        if (in_sizes[i] == N_NODES * D)           x  = (const float*)d_in[i];
        else if (in_sizes[i] == D * D)            Wm = (const float*)d_in[i];
        else if (in_sizes[i] == 2 * N_EDGES ||
                 in_sizes[i] == 4 * N_EDGES)      ei = d_in[i];
    }
    if (!x)  x  = (const float*)d_in[0];   // fallback: declared order
    if (!Wm) Wm = (const float*)d_in[1];
    if (!ei) ei = d_in[2];
    float* out = (float*)d_out;

    k_zero<<<1184, 256>>>((const int*)ei);

    k_degree<<<(N_EDGES + 255) / 256, 256>>>(ei);
    k_dinv<<<(N_NODES + 255) / 256, 256>>>();

    dim3 ggrid((N_NODES + GM - 1) / GM, D / GN);
    k_gemm<<<ggrid, 256>>>(x, Wm);        // writes g_xw internally (no symbol arg!)

    const int items = N_EDGES + N_NODES;
    k_scatter<<<(items + 7) / 8, 256>>>(ei);   // warp per item

    k_stats<<<592, D>>>();
    k_finalize_stats<<<1, D>>>();

    const int n4 = N_NODES * D / 4;
    k_output<<<(n4 + 255) / 256, 256>>>(out);
}